// round 8
// baseline (speedup 1.0000x reference)
#include <cuda_runtime.h>
#include <cuda_bf16.h>

#define BQ 8
#define NQ 8192
#define MK 2048
#define CC 256
#define EPSW 1e-8f
#define GSZ 8
#define NGROUP (MK / GSZ)   // 256 groups of 8 points

// Compact per-query result: (w0, w1, bitcast(i0 | i1<<16), bitcast(i2))
__device__ float4 g_wp[BQ * NQ];

// ---------------------------------------------------------------------------
// f32x2 packed helpers
// ---------------------------------------------------------------------------
typedef unsigned long long u64t;
__device__ __forceinline__ u64t fma2(u64t a, u64t b, u64t c) {
    u64t d; asm("fma.rn.f32x2 %0, %1, %2, %3;" : "=l"(d) : "l"(a), "l"(b), "l"(c));
    return d;
}
__device__ __forceinline__ u64t add2(u64t a, u64t b) {
    u64t d; asm("add.rn.f32x2 %0, %1, %2;" : "=l"(d) : "l"(a), "l"(b));
    return d;
}
__device__ __forceinline__ u64t mul2(u64t a, u64t b) {
    u64t d; asm("mul.rn.f32x2 %0, %1, %2;" : "=l"(d) : "l"(a), "l"(b));
    return d;
}
__device__ __forceinline__ u64t pack2(float lo, float hi) {
    u64t d; asm("mov.b64 %0, {%1, %2};" : "=l"(d) : "f"(lo), "f"(hi));
    return d;
}
__device__ __forceinline__ void unpack2(u64t v, float& lo, float& hi) {
    asm("mov.b64 {%0, %1}, %2;" : "=f"(lo), "=f"(hi) : "l"(v));
}

// ---------------------------------------------------------------------------
// Exact finale + output for one query, given its 3 winning groups.
// ---------------------------------------------------------------------------
__device__ __forceinline__ void nn_finale(
    const float4* __restrict__ sXY, const float* __restrict__ sZ,
    int qa, int qb, int qc,
    float ux, float uy, float uz,
    float4* __restrict__ outp)
{
    // ascending group ids -> ascending point index order (jax tie-break)
    int ha = min(qa, min(qb, qc));
    int hc = max(qa, max(qb, qc));
    int hb = qa + qb + qc - ha - hc;
    int grp[3] = { ha, hb, hc };

    float d0 = 1e30f, d1 = 1e30f, d2v = 1e30f;
    int   i0 = 0, i1 = 0, i2 = 0;
#pragma unroll
    for (int t = 0; t < 3; t++) {
        const int mb = grp[t] * GSZ;
#pragma unroll
        for (int k = 0; k < GSZ; k++) {
            const int m = mb + k;
            const int p = m >> 1, h = m & 1;
            float4 XY = sXY[p];
            float kx = h ? XY.y : XY.x;
            float ky = h ? XY.w : XY.z;
            float kz = sZ[m];
            float dx = kx - ux, dy = ky - uy, dz = kz - uz;
            float d2 = fmaf(dx, dx, fmaf(dy, dy, dz * dz));
            bool c0b = d2 < d0, c1b = d2 < d1, c2b = d2 < d2v;
            float t0 = c0b ? d2 : d0;
            float t1 = c0b ? d0 : (c1b ? d2 : d1);
            float t2 = c1b ? d1 : (c2b ? d2 : d2v);
            int   j0 = c0b ? m  : i0;
            int   j1 = c0b ? i0 : (c1b ? m  : i1);
            int   j2 = c1b ? i1 : (c2b ? m  : i2);
            d0 = t0; d1 = t1; d2v = t2;
            i0 = j0; i1 = j1; i2 = j2;
        }
    }

    const float r0 = 1.0f / (d0 + EPSW);
    const float r1 = 1.0f / (d1 + EPSW);
    const float r2 = 1.0f / (d2v + EPSW);
    const float s  = 1.0f / (r0 + r1 + r2);
    *outp = make_float4(r0 * s, r1 * s,
                        __int_as_float(i0 | (i1 << 16)),
                        __int_as_float(i2));
}

// ---------------------------------------------------------------------------
// Kernel 1: three_nn + weights. EXACT d^2 everywhere (selection must match
// the reference ordering; approximations fail the 1e-3 gate).
// nn is smem-crossbar writeback bound: broadcast LDS.128 costs 4 cyc/warp
// regardless. Fix: TWO queries per thread share every load (halves crossbar
// bytes per query), with register pressure kept low: GSZ=8, pair scores
// folded immediately into 4 running mins per query (nothing long-lived).
// Block 64 threads, grid (NQ/128, BQ) = 512 blocks (3.46/SM balance).
// ---------------------------------------------------------------------------
__global__ void __launch_bounds__(64) nn_kernel(
    const float* __restrict__ unknown,   // (B, N, 3)
    const float* __restrict__ known)     // (B, M, 3)
{
    __shared__ float4 sXY[MK / 2];   // (x0,x1,y0,y1) per point-pair, 16 KB
    __shared__ float  sZ[MK];        // 8 KB

    const int b = blockIdx.y;
    {
        const float2* kb2 = (const float2*)(known + (size_t)b * MK * 3);
        for (int i = threadIdx.x; i < MK / 2; i += 64) {
            float2 p0 = kb2[i * 3 + 0];   // x0 y0
            float2 p1 = kb2[i * 3 + 1];   // z0 x1
            float2 p2 = kb2[i * 3 + 2];   // y1 z1
            sXY[i] = make_float4(p0.x, p1.y, p0.y, p2.x);
            sZ[2 * i]     = p1.x;
            sZ[2 * i + 1] = p2.y;
        }
    }
    __syncthreads();

    const int nA = blockIdx.x * 128 + threadIdx.x;
    const int nB = nA + 64;
    const float* uA = unknown + ((size_t)b * NQ + nA) * 3;
    const float* uB = unknown + ((size_t)b * NQ + nB) * 3;
    const float axc = uA[0], ayc = uA[1], azc = uA[2];
    const float bxc = uB[0], byc = uB[1], bzc = uB[2];
    const u64t nax = pack2(-axc, -axc), nay = pack2(-ayc, -ayc), naz = pack2(-azc, -azc);
    const u64t nbx = pack2(-bxc, -bxc), nby = pack2(-byc, -byc), nbz = pack2(-bzc, -bzc);

    // per-query top-3 group mins (ascending) + group ids
    float va0 = 1e30f, va1 = 1e30f, va2 = 1e30f;
    int   qa0 = 0, qa1 = 0, qa2 = 0;
    float vb0 = 1e30f, vb1 = 1e30f, vb2 = 1e30f;
    int   qb0 = 0, qb1 = 0, qb2 = 0;

    const ulonglong2* pXY = (const ulonglong2*)sXY;
    const ulonglong2* pZ  = (const ulonglong2*)sZ;

#pragma unroll 2
    for (int g = 0; g < NGROUP; g++) {
        // 4 point-pairs; fold each pair's scores straight into running mins
        float ra0, ra1, ra2, ra3;     // query A running pair-mins
        float rb0, rb1, rb2, rb3;     // query B running pair-mins
        {
            ulonglong2 A = pXY[4 * g + 0];
            ulonglong2 Zp = pZ[2 * g + 0];
            u64t dxa = add2(A.x, nax), dya = add2(A.y, nay), dza = add2(Zp.x, naz);
            float lo, hi;
            unpack2(fma2(dxa, dxa, fma2(dya, dya, mul2(dza, dza))), lo, hi);
            ra0 = fminf(lo, hi);
            u64t dxb = add2(A.x, nbx), dyb = add2(A.y, nby), dzb = add2(Zp.x, nbz);
            unpack2(fma2(dxb, dxb, fma2(dyb, dyb, mul2(dzb, dzb))), lo, hi);
            rb0 = fminf(lo, hi);

            ulonglong2 A1 = pXY[4 * g + 1];
            u64t ex = add2(A1.x, nax), ey = add2(A1.y, nay), ez = add2(Zp.y, naz);
            unpack2(fma2(ex, ex, fma2(ey, ey, mul2(ez, ez))), lo, hi);
            ra1 = fminf(lo, hi);
            u64t fx = add2(A1.x, nbx), fy = add2(A1.y, nby), fz = add2(Zp.y, nbz);
            unpack2(fma2(fx, fx, fma2(fy, fy, mul2(fz, fz))), lo, hi);
            rb1 = fminf(lo, hi);
        }
        {
            ulonglong2 A = pXY[4 * g + 2];
            ulonglong2 Zp = pZ[2 * g + 1];
            u64t dxa = add2(A.x, nax), dya = add2(A.y, nay), dza = add2(Zp.x, naz);
            float lo, hi;
            unpack2(fma2(dxa, dxa, fma2(dya, dya, mul2(dza, dza))), lo, hi);
            ra2 = fminf(lo, hi);
            u64t dxb = add2(A.x, nbx), dyb = add2(A.y, nby), dzb = add2(Zp.x, nbz);
            unpack2(fma2(dxb, dxb, fma2(dyb, dyb, mul2(dzb, dzb))), lo, hi);
            rb2 = fminf(lo, hi);

            ulonglong2 A1 = pXY[4 * g + 3];
            u64t ex = add2(A1.x, nax), ey = add2(A1.y, nay), ez = add2(Zp.y, naz);
            unpack2(fma2(ex, ex, fma2(ey, ey, mul2(ez, ez))), lo, hi);
            ra3 = fminf(lo, hi);
            u64t fx = add2(A1.x, nbx), fy = add2(A1.y, nby), fz = add2(Zp.y, nbz);
            unpack2(fma2(fx, fx, fma2(fy, fy, mul2(fz, fz))), lo, hi);
            rb3 = fminf(lo, hi);
        }

        float ma  = fminf(fminf(ra0, ra1), fminf(ra2, ra3));
        float mbv = fminf(fminf(rb0, rb1), fminf(rb2, rb3));

        // branchless sorted inserts; strict < keeps earlier (lower g)
        {
            bool c0 = ma < va0, c1 = ma < va1, c2 = ma < va2;
            float nv0 = c0 ? ma  : va0;
            float nv1 = c0 ? va0 : (c1 ? ma  : va1);
            float nv2 = c1 ? va1 : (c2 ? ma  : va2);
            int   ng0 = c0 ? g   : qa0;
            int   ng1 = c0 ? qa0 : (c1 ? g   : qa1);
            int   ng2 = c1 ? qa1 : (c2 ? g   : qa2);
            va0 = nv0; va1 = nv1; va2 = nv2;
            qa0 = ng0; qa1 = ng1; qa2 = ng2;
        }
        {
            bool c0 = mbv < vb0, c1 = mbv < vb1, c2 = mbv < vb2;
            float nv0 = c0 ? mbv : vb0;
            float nv1 = c0 ? vb0 : (c1 ? mbv : vb1);
            float nv2 = c1 ? vb1 : (c2 ? mbv : vb2);
            int   ng0 = c0 ? g   : qb0;
            int   ng1 = c0 ? qb0 : (c1 ? g   : qb1);
            int   ng2 = c1 ? qb1 : (c2 ? g   : qb2);
            vb0 = nv0; vb1 = nv1; vb2 = nv2;
            qb0 = ng0; qb1 = ng1; qb2 = ng2;
        }
    }

    nn_finale(sXY, sZ, qa0, qa1, qa2, axc, ayc, azc, &g_wp[(size_t)b * NQ + nA]);
    nn_finale(sXY, sZ, qb0, qb1, qb2, bxc, byc, bzc, &g_wp[(size_t)b * NQ + nB]);
}

// ---------------------------------------------------------------------------
// Kernel 2: three_interpolate, m-major transposed smem + packed f32x2 FMAs.
// Grid (CC/4, BQ) = 512 blocks, block 256. smem rowsT[m][c0..c0+3] (32 KB).
// ---------------------------------------------------------------------------
#define CG 4

__global__ void __launch_bounds__(256) interp_kernel(
    const float* __restrict__ feats,     // (B, C, M)
    float* __restrict__ out)             // (B, C, N)
{
    __shared__ float rowsT[MK * CG];     // 32 KB

    const int b  = blockIdx.y;
    const int c0 = blockIdx.x * CG;

    {
        const float* fp = feats + ((size_t)b * CC + c0) * MK;
#pragma unroll
        for (int it = 0; it < MK / 256; it++) {
            const int m = it * 256 + threadIdx.x;
            float a  = fp[m];
            float bb = fp[MK + m];
            float c  = fp[2 * MK + m];
            float d  = fp[3 * MK + m];
            *(float4*)&rowsT[m * 4] = make_float4(a, bb, c, d);
        }
    }
    __syncthreads();

    const float4* wp = (const float4*)&g_wp[(size_t)b * NQ];
    float* outp = out + ((size_t)b * CC + c0) * NQ;

#pragma unroll 2
    for (int it = 0; it < NQ / 1024; it++) {   // 8 iters
        const int n0 = it * 1024 + threadIdx.x * 4;

        float vq[4][4];   // [query][channel]
#pragma unroll
        for (int q = 0; q < 4; q++) {
            float4 W = wp[n0 + q];
            float w0 = W.x, w1 = W.y;
            float w2 = 1.0f - w0 - w1;
            unsigned pk = __float_as_uint(W.z);
            int j0 = pk & 0xFFFF;
            int j1 = pk >> 16;
            int j2 = __float_as_uint(W.w);

            ulonglong2 f0 = *(const ulonglong2*)&rowsT[j0 * 4];
            ulonglong2 f1 = *(const ulonglong2*)&rowsT[j1 * 4];
            ulonglong2 f2 = *(const ulonglong2*)&rowsT[j2 * 4];

            u64t w0p = pack2(w0, w0);
            u64t w1p = pack2(w1, w1);
            u64t w2p = pack2(w2, w2);

            u64t lo = fma2(w0p, f0.x, fma2(w1p, f1.x, mul2(w2p, f2.x)));
            u64t hi = fma2(w0p, f0.y, fma2(w1p, f1.y, mul2(w2p, f2.y)));
            unpack2(lo, vq[q][0], vq[q][1]);
            unpack2(hi, vq[q][2], vq[q][3]);
        }

#pragma unroll
        for (int c = 0; c < CG; c++) {
            float4 v = make_float4(vq[0][c], vq[1][c], vq[2][c], vq[3][c]);
            *(float4*)(outp + (size_t)c * NQ + n0) = v;
        }
    }
}

// ---------------------------------------------------------------------------
// Launch
// ---------------------------------------------------------------------------
extern "C" void kernel_launch(void* const* d_in, const int* in_sizes, int n_in,
                              void* d_out, int out_size)
{
    const float* unknown = (const float*)d_in[0];   // (8, 8192, 3)
    const float* known   = (const float*)d_in[1];   // (8, 2048, 3)
    const float* feats   = (const float*)d_in[2];   // (8, 256, 2048)
    float* out = (float*)d_out;                     // (8, 256, 8192)

    dim3 g1(NQ / 128, BQ);
    nn_kernel<<<g1, 64>>>(unknown, known);

    dim3 g2(CC / CG, BQ);
    interp_kernel<<<g2, 256>>>(feats, out);
}

// round 9
// speedup vs baseline: 1.7172x; 1.7172x over previous
#include <cuda_runtime.h>
#include <cuda_bf16.h>

#define BQ 8
#define NQ 8192
#define MK 2048
#define CC 256
#define EPSW 1e-8f
#define GSZ 8
#define NGROUP (MK / GSZ)   // 256 groups of 8 points

// Compact per-query result: (w0, w1, bitcast(i0 | i1<<16), bitcast(i2))
__device__ float4 g_wp[BQ * NQ];

// ---------------------------------------------------------------------------
// f32x2 packed helpers
// ---------------------------------------------------------------------------
typedef unsigned long long u64t;
__device__ __forceinline__ u64t fma2(u64t a, u64t b, u64t c) {
    u64t d; asm("fma.rn.f32x2 %0, %1, %2, %3;" : "=l"(d) : "l"(a), "l"(b), "l"(c));
    return d;
}
__device__ __forceinline__ u64t add2(u64t a, u64t b) {
    u64t d; asm("add.rn.f32x2 %0, %1, %2;" : "=l"(d) : "l"(a), "l"(b));
    return d;
}
__device__ __forceinline__ u64t mul2(u64t a, u64t b) {
    u64t d; asm("mul.rn.f32x2 %0, %1, %2;" : "=l"(d) : "l"(a), "l"(b));
    return d;
}
__device__ __forceinline__ u64t pack2(float lo, float hi) {
    u64t d; asm("mov.b64 %0, {%1, %2};" : "=l"(d) : "f"(lo), "f"(hi));
    return d;
}
__device__ __forceinline__ void unpack2(u64t v, float& lo, float& hi) {
    asm("mov.b64 {%0, %1}, %2;" : "=f"(lo), "=f"(hi) : "l"(v));
}

// ---------------------------------------------------------------------------
// Kernel 1: three_nn + weights — EXACT d^2 (selection must reproduce the
// reference ordering; any approximation fails the 1e-3 gate). This is the
// R4 configuration verbatim (measured 43.0 us, rel_err 1.04e-7): block 128,
// 1 query/thread, grid 512; groups of 8 ranked by exact group-min; exact
// top-3 finale over 24 candidates. Occupancy is work-limited (13.8 warps/SM)
// and this structure is its measured optimum.
// ---------------------------------------------------------------------------
__global__ void __launch_bounds__(128) nn_kernel(
    const float* __restrict__ unknown,   // (B, N, 3)
    const float* __restrict__ known)     // (B, M, 3)
{
    __shared__ float4 sXY[MK / 2];   // (x0,x1,y0,y1) per point-pair, 16 KB
    __shared__ float  sZ[MK];        // 8 KB

    const int b = blockIdx.y;
    {
        const float2* kb2 = (const float2*)(known + (size_t)b * MK * 3);
        for (int i = threadIdx.x; i < MK / 2; i += 128) {
            float2 p0 = kb2[i * 3 + 0];   // x0 y0
            float2 p1 = kb2[i * 3 + 1];   // z0 x1
            float2 p2 = kb2[i * 3 + 2];   // y1 z1
            sXY[i] = make_float4(p0.x, p1.y, p0.y, p2.x);
            sZ[2 * i]     = p1.x;
            sZ[2 * i + 1] = p2.y;
        }
    }
    __syncthreads();

    const int n = blockIdx.x * 128 + threadIdx.x;
    const float* u = unknown + ((size_t)b * NQ + n) * 3;
    const float ux = u[0], uy = u[1], uz = u[2];
    const u64t nux = pack2(-ux, -ux);
    const u64t nuy = pack2(-uy, -uy);
    const u64t nuz = pack2(-uz, -uz);

    // top-3 group mins (sorted ascending) + group ids
    float v0 = 1e30f, v1 = 1e30f, v2 = 1e30f;
    int   q0 = 0, q1 = 0, q2 = 0;

    const ulonglong2* pXY = (const ulonglong2*)sXY;
    const ulonglong2* pZ  = (const ulonglong2*)sZ;

#pragma unroll 4
    for (int g = 0; g < NGROUP; g++) {
        ulonglong2 A0 = pXY[4 * g + 0];
        ulonglong2 A1 = pXY[4 * g + 1];
        ulonglong2 A2 = pXY[4 * g + 2];
        ulonglong2 A3 = pXY[4 * g + 3];
        ulonglong2 Z0 = pZ[2 * g + 0];   // z[8g..8g+3]
        ulonglong2 Z1 = pZ[2 * g + 1];   // z[8g+4..8g+7]

        u64t dx0 = add2(A0.x, nux), dy0 = add2(A0.y, nuy), dz0 = add2(Z0.x, nuz);
        u64t dx1 = add2(A1.x, nux), dy1 = add2(A1.y, nuy), dz1 = add2(Z0.y, nuz);
        u64t dx2 = add2(A2.x, nux), dy2 = add2(A2.y, nuy), dz2 = add2(Z1.x, nuz);
        u64t dx3 = add2(A3.x, nux), dy3 = add2(A3.y, nuy), dz3 = add2(Z1.y, nuz);

        u64t a0 = fma2(dx0, dx0, fma2(dy0, dy0, mul2(dz0, dz0)));
        u64t a1 = fma2(dx1, dx1, fma2(dy1, dy1, mul2(dz1, dz1)));
        u64t a2 = fma2(dx2, dx2, fma2(dy2, dy2, mul2(dz2, dz2)));
        u64t a3 = fma2(dx3, dx3, fma2(dy3, dy3, mul2(dz3, dz3)));

        float s0, s1, s2, s3, s4, s5, s6, s7;
        unpack2(a0, s0, s1); unpack2(a1, s2, s3);
        unpack2(a2, s4, s5); unpack2(a3, s6, s7);

        float m = fminf(fminf(fminf(s0, s1), fminf(s2, s3)),
                        fminf(fminf(s4, s5), fminf(s6, s7)));

        // branchless sorted insert of (m, g); strict < keeps earlier (lower g)
        bool c0 = m < v0, c1 = m < v1, c2 = m < v2;
        float nv0 = c0 ? m  : v0;
        float nv1 = c0 ? v0 : (c1 ? m  : v1);
        float nv2 = c1 ? v1 : (c2 ? m  : v2);
        int   ng0 = c0 ? g  : q0;
        int   ng1 = c0 ? q0 : (c1 ? g  : q1);
        int   ng2 = c1 ? q1 : (c2 ? g  : q2);
        v0 = nv0; v1 = nv1; v2 = nv2;
        q0 = ng0; q1 = ng1; q2 = ng2;
    }

    // Iterate winning groups in ascending id (jax lower-index tie-break).
    int ha = min(q0, min(q1, q2));
    int hc = max(q0, max(q1, q2));
    int hb = q0 + q1 + q2 - ha - hc;
    int grp[3] = { ha, hb, hc };

    // Finale: exact top-3 over the 24 candidate points.
    float d0 = 1e30f, d1 = 1e30f, d2v = 1e30f;
    int   i0 = 0, i1 = 0, i2 = 0;
#pragma unroll
    for (int t = 0; t < 3; t++) {
        const int mb = grp[t] * GSZ;
#pragma unroll
        for (int k = 0; k < GSZ; k++) {
            const int m = mb + k;
            const int p = m >> 1, h = m & 1;
            float4 XY = sXY[p];
            float kx = h ? XY.y : XY.x;
            float ky = h ? XY.w : XY.z;
            float kz = sZ[m];
            float dx = kx - ux, dy = ky - uy, dz = kz - uz;
            float d2 = fmaf(dx, dx, fmaf(dy, dy, dz * dz));
            bool c0b = d2 < d0, c1b = d2 < d1, c2b = d2 < d2v;
            float t0 = c0b ? d2 : d0;
            float t1 = c0b ? d0 : (c1b ? d2 : d1);
            float t2 = c1b ? d1 : (c2b ? d2 : d2v);
            int   j0 = c0b ? m  : i0;
            int   j1 = c0b ? i0 : (c1b ? m  : i1);
            int   j2 = c1b ? i1 : (c2b ? m  : i2);
            d0 = t0; d1 = t1; d2v = t2;
            i0 = j0; i1 = j1; i2 = j2;
        }
    }

    const float r0 = 1.0f / (d0 + EPSW);
    const float r1 = 1.0f / (d1 + EPSW);
    const float r2 = 1.0f / (d2v + EPSW);
    const float s  = 1.0f / (r0 + r1 + r2);
    g_wp[(size_t)b * NQ + n] =
        make_float4(r0 * s, r1 * s,
                    __int_as_float(i0 | (i1 << 16)),
                    __int_as_float(i2));
}

// ---------------------------------------------------------------------------
// Kernel 2: three_interpolate with explicit gather front-batching.
// Grid (CC/4, BQ) = 512 blocks, block 256, smem rowsT[m][c0..c0+3] (32 KB).
// Per iteration: load 4 queries' (idx,weight), issue ALL 12 LDS.128 gathers
// into named registers (MLP=12 instead of ~3), THEN consume and store.
// ---------------------------------------------------------------------------
#define CG 4

__global__ void __launch_bounds__(256) interp_kernel(
    const float* __restrict__ feats,     // (B, C, M)
    float* __restrict__ out)             // (B, C, N)
{
    __shared__ float rowsT[MK * CG];     // 32 KB

    const int b  = blockIdx.y;
    const int c0 = blockIdx.x * CG;

    {
        const float* fp = feats + ((size_t)b * CC + c0) * MK;
#pragma unroll
        for (int it = 0; it < MK / 256; it++) {
            const int m = it * 256 + threadIdx.x;
            float a  = fp[m];
            float bb = fp[MK + m];
            float c  = fp[2 * MK + m];
            float d  = fp[3 * MK + m];
            *(float4*)&rowsT[m * 4] = make_float4(a, bb, c, d);
        }
    }
    __syncthreads();

    const float4* wp = (const float4*)&g_wp[(size_t)b * NQ];
    float* outp = out + ((size_t)b * CC + c0) * NQ;

    for (int it = 0; it < NQ / 1024; it++) {   // 8 iters
        const int n0 = it * 1024 + threadIdx.x * 4;

        // --- phase 1: load weights/indices for 4 queries ---
        float4 W0 = wp[n0 + 0];
        float4 W1 = wp[n0 + 1];
        float4 W2 = wp[n0 + 2];
        float4 W3 = wp[n0 + 3];

        int j[12];
        {
            unsigned pk0 = __float_as_uint(W0.z);
            unsigned pk1 = __float_as_uint(W1.z);
            unsigned pk2 = __float_as_uint(W2.z);
            unsigned pk3 = __float_as_uint(W3.z);
            j[0]  = pk0 & 0xFFFF; j[1]  = pk0 >> 16; j[2]  = __float_as_uint(W0.w);
            j[3]  = pk1 & 0xFFFF; j[4]  = pk1 >> 16; j[5]  = __float_as_uint(W1.w);
            j[6]  = pk2 & 0xFFFF; j[7]  = pk2 >> 16; j[8]  = __float_as_uint(W2.w);
            j[9]  = pk3 & 0xFFFF; j[10] = pk3 >> 16; j[11] = __float_as_uint(W3.w);
        }

        // --- phase 2: issue all 12 gathers before any consumption ---
        ulonglong2 f[12];
#pragma unroll
        for (int t = 0; t < 12; t++)
            f[t] = *(const ulonglong2*)&rowsT[j[t] * 4];

        // --- phase 3: consume ---
        float vq[4][4];   // [query][channel]
        const float4 Wv[4] = { W0, W1, W2, W3 };
#pragma unroll
        for (int q = 0; q < 4; q++) {
            float w0 = Wv[q].x, w1 = Wv[q].y;
            float w2 = 1.0f - w0 - w1;
            u64t w0p = pack2(w0, w0);
            u64t w1p = pack2(w1, w1);
            u64t w2p = pack2(w2, w2);
            u64t lo = fma2(w0p, f[3*q].x, fma2(w1p, f[3*q+1].x, mul2(w2p, f[3*q+2].x)));
            u64t hi = fma2(w0p, f[3*q].y, fma2(w1p, f[3*q+1].y, mul2(w2p, f[3*q+2].y)));
            unpack2(lo, vq[q][0], vq[q][1]);
            unpack2(hi, vq[q][2], vq[q][3]);
        }

#pragma unroll
        for (int c = 0; c < CG; c++) {
            float4 v = make_float4(vq[0][c], vq[1][c], vq[2][c], vq[3][c]);
            *(float4*)(outp + (size_t)c * NQ + n0) = v;
        }
    }
}

// ---------------------------------------------------------------------------
// Launch
// ---------------------------------------------------------------------------
extern "C" void kernel_launch(void* const* d_in, const int* in_sizes, int n_in,
                              void* d_out, int out_size)
{
    const float* unknown = (const float*)d_in[0];   // (8, 8192, 3)
    const float* known   = (const float*)d_in[1];   // (8, 2048, 3)
    const float* feats   = (const float*)d_in[2];   // (8, 256, 2048)
    float* out = (float*)d_out;                     // (8, 256, 8192)

    dim3 g1(NQ / 128, BQ);
    nn_kernel<<<g1, 128>>>(unknown, known);

    dim3 g2(CC / CG, BQ);
    interp_kernel<<<g2, 256>>>(feats, out);
}